// round 2
// baseline (speedup 1.0000x reference)
#include <cuda_runtime.h>
#include <math.h>

#define BN 16
#define HH 288
#define WW 384
#define NPTS (HH*WW)          // 110592
#define NITER 5
#define BPB 27                // blocks per batch
#define TPB 256
#define STRIDE (BPB*TPB)      // 6912 = 18*384 -> px loop-invariant
#define KITER (NPTS/STRIDE)   // 16 points per thread
#define NACC 26               // 20 unique nonzero JTJ + 6 JTr

// persistent device state (zero at module load; reset in-kernel each launch)
__device__ double   g_acc[BN][NACC];
__device__ float    g_dR[BN][9];    // R = I + dR  (zero-init == identity)
__device__ float    g_t[BN][3];
__device__ unsigned g_cnt[BN];      // monotonic arrivals within a launch
__device__ unsigned g_iter[BN];     // completed solves for batch b

__device__ __forceinline__ unsigned ld_acq(const unsigned* p) {
    unsigned v;
    asm volatile("ld.global.acquire.gpu.u32 %0, [%1];" : "=r"(v) : "l"(p) : "memory");
    return v;
}
__device__ __forceinline__ void st_rel(unsigned* p, unsigned v) {
    asm volatile("st.global.release.gpu.u32 [%0], %1;" :: "l"(p), "r"(v) : "memory");
}

// map of upper-tri (i,j) -> acc slot, skipping the structurally-zero (0,1):
// (0,0)=0 (0,2)=1 (0,3)=2 (0,4)=3 (0,5)=4 (1,1)=5 (1,2)=6 (1,3)=7 (1,4)=8 (1,5)=9
// (2,2)=10 (2,3)=11 (2,4)=12 (2,5)=13 (3,3)=14 (3,4)=15 (3,5)=16 (4,4)=17 (4,5)=18 (5,5)=19
// JTr: 20..25

__device__ void solve_batch(int b, int it) {
    // read accumulators from L2 (coherent point)
    double m[NACC];
#pragma unroll
    for (int k = 0; k < NACC; k++) m[k] = __ldcg(&g_acc[b][k]);

    double A[6][7];
    A[0][0]=m[0];            A[0][1]=0.0;  A[0][2]=m[1]; A[0][3]=m[2];  A[0][4]=m[3];  A[0][5]=m[4];
    A[1][0]=0.0;             A[1][1]=m[5]; A[1][2]=m[6]; A[1][3]=m[7];  A[1][4]=m[8];  A[1][5]=m[9];
    A[2][0]=m[1]; A[2][1]=m[6];  A[2][2]=m[10]; A[2][3]=m[11]; A[2][4]=m[12]; A[2][5]=m[13];
    A[3][0]=m[2]; A[3][1]=m[7];  A[3][2]=m[11]; A[3][3]=m[14]; A[3][4]=m[15]; A[3][5]=m[16];
    A[4][0]=m[3]; A[4][1]=m[8];  A[4][2]=m[12]; A[4][3]=m[15]; A[4][4]=m[17]; A[4][5]=m[18];
    A[5][0]=m[4]; A[5][1]=m[9];  A[5][2]=m[13]; A[5][3]=m[16]; A[5][4]=m[17+1]; A[5][5]=m[19];
    // fix typo-proof: A[5][4] must be m[18]
    A[5][4]=m[18];

    const double tr = A[0][0]+A[1][1]+A[2][2]+A[3][3]+A[4][4]+A[5][5];
    const double damp = 1e-4 * tr / 6.0 + 1e-6;
    for (int i = 0; i < 6; i++) { A[i][i] += damp; A[i][6] = -m[20 + i]; }

    // Gaussian elimination with partial pivoting
    for (int col = 0; col < 6; col++) {
        int piv = col; double best = fabs(A[col][col]);
        for (int r = col + 1; r < 6; r++) {
            double v = fabs(A[r][col]);
            if (v > best) { best = v; piv = r; }
        }
        if (piv != col)
            for (int q = col; q < 7; q++) { double tmp = A[col][q]; A[col][q] = A[piv][q]; A[piv][q] = tmp; }
        const double inv = 1.0 / A[col][col];
        for (int r = col + 1; r < 6; r++) {
            const double f = A[r][col] * inv;
            for (int q = col; q < 7; q++) A[r][q] -= f * A[col][q];
        }
    }
    double dx[6];
    for (int i = 5; i >= 0; i--) {
        double s = A[i][6];
        for (int j = i + 1; j < 6; j++) s -= A[i][j] * dx[j];
        dx[i] = s / A[i][i];
    }

    g_t[b][0] += (float)dx[0];
    g_t[b][1] += (float)dx[1];
    g_t[b][2] += (float)dx[2];

    // R_new = exp_so3(dx[3:]) @ (I + dR_old);   store dR_new = R_new - I
    const double wx = dx[3], wy = dx[4], wz = dx[5];
    double th = sqrt(wx*wx + wy*wy + wz*wz);
    if (th < 1e-8) th = 1e-8;
    const double ux = wx/th, uy = wy/th, uz = wz/th;
    const double st = sin(th), ct = cos(th), vt = 1.0 - ct;
    double E[3][3] = {
        { ct + vt*ux*ux,      vt*ux*uy - st*uz, vt*ux*uz + st*uy },
        { vt*uy*ux + st*uz,   ct + vt*uy*uy,    vt*uy*uz - st*ux },
        { vt*uz*ux - st*uy,   vt*uz*uy + st*ux, ct + vt*uz*uz }
    };
    double Ro[3][3];
    for (int i = 0; i < 3; i++)
        for (int j = 0; j < 3; j++)
            Ro[i][j] = (double)g_dR[b][i*3+j] + (i == j ? 1.0 : 0.0);
    for (int i = 0; i < 3; i++)
        for (int j = 0; j < 3; j++) {
            double r = E[i][0]*Ro[0][j] + E[i][1]*Ro[1][j] + E[i][2]*Ro[2][j];
            g_dR[b][i*3+j] = (float)(r - (i == j ? 1.0 : 0.0));
        }

    // zero accumulators for the next iteration of this batch
#pragma unroll
    for (int k = 0; k < NACC; k++) g_acc[b][k] = 0.0;

    __threadfence();
    st_rel(&g_iter[b], (unsigned)(it + 1));
}

__global__ void __launch_bounds__(TPB, 3) fused_kernel(
    const float* __restrict__ pts,
    const float* __restrict__ conf,
    const float* __restrict__ Kin,
    const float* __restrict__ pose,
    float* __restrict__ out)
{
    const int b = blockIdx.y;
    const int tid = threadIdx.x;

    const float fx = Kin[b*9 + 0], cx = Kin[b*9 + 2];
    const float fy = Kin[b*9 + 4], cy = Kin[b*9 + 5];

    // delta over the fixed pixel grid (compile-time constant)
    const float delta = 0.1f * sqrtf(((float)WW*(float)WW - 1.f)/12.f +
                                     ((float)HH*(float)HH - 1.f)/12.f);

    const int base = blockIdx.x * TPB + tid;                 // 0..6911
    const float px = (float)(base % WW);
    const int   py0 = base / WW;                             // py = py0 + 18*k

    const float* __restrict__ Pbase  = pts  + (size_t)b * NPTS * 3 + (size_t)3 * base;
    const float* __restrict__ Cbase  = conf + (size_t)b * NPTS + base;

    __shared__ float sRt[12];
    __shared__ float sm[TPB/32][NACC];

    for (int it = 0; it < NITER; it++) {
        if (tid == 0) {
            while (ld_acq(&g_iter[b]) < (unsigned)it) __nanosleep(64);
#pragma unroll
            for (int j = 0; j < 9; j++) sRt[j] = __ldcg(&g_dR[b][j]);
#pragma unroll
            for (int j = 0; j < 3; j++) sRt[9+j] = __ldcg(&g_t[b][j]);
        }
        __syncthreads();

        const float R00 = 1.f + sRt[0], R01 = sRt[1],       R02 = sRt[2];
        const float R10 = sRt[3],       R11 = 1.f + sRt[4], R12 = sRt[5];
        const float R20 = sRt[6],       R21 = sRt[7],       R22 = 1.f + sRt[8];
        const float t0 = sRt[9], t1 = sRt[10], t2 = sRt[11];

        float acc[NACC];
#pragma unroll
        for (int k = 0; k < NACC; k++) acc[k] = 0.f;

#pragma unroll 4
        for (int k = 0; k < KITER; k++) {
            const float p0 = Pbase[3*STRIDE*k + 0];
            const float p1 = Pbase[3*STRIDE*k + 1];
            const float p2 = Pbase[3*STRIDE*k + 2];
            const float w  = Cbase[STRIDE*k];
            const float py = (float)(py0 + (HH/KITER)*k);

            const float X  = fmaf(R00, p0, fmaf(R01, p1, fmaf(R02, p2, t0)));
            const float Y  = fmaf(R10, p0, fmaf(R11, p1, fmaf(R12, p2, t1)));
            const float Zc = fmaf(R20, p0, fmaf(R21, p1, fmaf(R22, p2, t2)));
            const float z  = fmaxf(Zc, 0.01f);
            const float iz = __fdividef(1.0f, z);

            const float fxiz = fx * iz, fyiz = fy * iz;
            const float rx = fmaf(fxiz, X, cx) - px;
            const float ry = fmaf(fyiz, Y, cy) - py;
            const float wrx = w * rx, wry = w * ry;
            const float q  = fmaf(wrx, wrx, wry * wry);
            // s = w^2 * min(1, delta / max(rn,1e-8)) ; rn = sqrt(q)
            const float inv_rn = __frsqrt_rn(fmaxf(q, 1e-16f));
            const float s = (w * w) * fminf(1.f, delta * inv_rn);

            const float Xiz = X * iz, Yiz = Y * iz;
            const float u0 = fxiz;                 // a
            const float u2 = -fxiz * Xiz;          // bb
            const float u3 = u2 * Y;
            const float u4 = fmaf(u0, Zc, -u2 * X);
            const float u5 = -u0 * Y;
            const float v1 = fyiz;                 // c
            const float v2 = -fyiz * Yiz;          // d
            const float v3 = fmaf(v2, Y, -v1 * Zc);
            const float v4 = -v2 * X;
            const float v5 = v1 * X;

            const float su0 = s*u0, su2 = s*u2, su3 = s*u3, su4 = s*u4, su5 = s*u5;
            const float sv1 = s*v1, sv2 = s*v2, sv3 = s*v3, sv4 = s*v4, sv5 = s*v5;

            acc[0]  = fmaf(su0, u0, acc[0]);
            acc[1]  = fmaf(su0, u2, acc[1]);
            acc[2]  = fmaf(su0, u3, acc[2]);
            acc[3]  = fmaf(su0, u4, acc[3]);
            acc[4]  = fmaf(su0, u5, acc[4]);
            acc[5]  = fmaf(sv1, v1, acc[5]);
            acc[6]  = fmaf(sv1, v2, acc[6]);
            acc[7]  = fmaf(sv1, v3, acc[7]);
            acc[8]  = fmaf(sv1, v4, acc[8]);
            acc[9]  = fmaf(sv1, v5, acc[9]);
            acc[10] = fmaf(su2, u2, fmaf(sv2, v2, acc[10]));
            acc[11] = fmaf(su2, u3, fmaf(sv2, v3, acc[11]));
            acc[12] = fmaf(su2, u4, fmaf(sv2, v4, acc[12]));
            acc[13] = fmaf(su2, u5, fmaf(sv2, v5, acc[13]));
            acc[14] = fmaf(su3, u3, fmaf(sv3, v3, acc[14]));
            acc[15] = fmaf(su3, u4, fmaf(sv3, v4, acc[15]));
            acc[16] = fmaf(su3, u5, fmaf(sv3, v5, acc[16]));
            acc[17] = fmaf(su4, u4, fmaf(sv4, v4, acc[17]));
            acc[18] = fmaf(su4, u5, fmaf(sv4, v5, acc[18]));
            acc[19] = fmaf(su5, u5, fmaf(sv5, v5, acc[19]));

            const float srx = s * rx, sry = s * ry;
            acc[20] = fmaf(srx, u0, acc[20]);
            acc[21] = fmaf(sry, v1, acc[21]);
            acc[22] = fmaf(srx, u2, fmaf(sry, v2, acc[22]));
            acc[23] = fmaf(srx, u3, fmaf(sry, v3, acc[23]));
            acc[24] = fmaf(srx, u4, fmaf(sry, v4, acc[24]));
            acc[25] = fmaf(srx, u5, fmaf(sry, v5, acc[25]));
        }

        // warp tree-reduce each of NACC sums
#pragma unroll
        for (int k = 0; k < NACC; k++) {
            float v = acc[k];
#pragma unroll
            for (int o = 16; o > 0; o >>= 1) v += __shfl_down_sync(0xffffffffu, v, o);
            acc[k] = v;
        }
        const int wid = tid >> 5, lane = tid & 31;
        if (lane == 0) {
#pragma unroll
            for (int k = 0; k < NACC; k++) sm[wid][k] = acc[k];
        }
        __syncthreads();
        if (tid < NACC) {
            double v = 0.0;
#pragma unroll
            for (int wv = 0; wv < TPB/32; wv++) v += (double)sm[wv][tid];
            atomicAdd(&g_acc[b][tid], v);
            __threadfence();
        }
        __syncthreads();

        if (tid == 0) {
            unsigned old = atomicAdd(&g_cnt[b], 1u);
            if (old == (unsigned)((it + 1) * BPB - 1)) {
                __threadfence();
                solve_batch(b, it);   // ends with release-store of g_iter[b]
            }
        }
        __syncthreads();   // protect sRt / sm reuse next iteration
    }

    // -------- final loss + state reset (one designated thread) --------
    if (blockIdx.x == 0 && blockIdx.y == 0 && tid == 0) {
        for (int bb = 0; bb < BN; bb++)
            while (ld_acq(&g_iter[bb]) < (unsigned)NITER) __nanosleep(64);
        __threadfence();

        double Rp[BN][3][3], tp[BN][3];
        for (int bb = 0; bb < BN; bb++) {
            for (int i = 0; i < 3; i++) {
                for (int j = 0; j < 3; j++)
                    Rp[bb][i][j] = (double)__ldcg(&g_dR[bb][i*3+j]) + (i == j ? 1.0 : 0.0);
                tp[bb][i] = (double)__ldcg(&g_t[bb][i]);
            }
        }

        const double hi = (double)(float)(1.0 - 1e-7);
        const double lo = (double)(float)(-1.0 + 1e-7);

        double R0g[3][3], t0g[3];
        for (int i = 0; i < 3; i++) {
            for (int j = 0; j < 3; j++) R0g[i][j] = (double)pose[i*4+j];
            t0g[i] = (double)pose[i*4+3];
        }

        double rot_sum = 0.0, trans_sum = 0.0;
        for (int bb = 0; bb < BN; bb++) {
            double Rbg[3][3], tbg[3];
            for (int i = 0; i < 3; i++) {
                for (int j = 0; j < 3; j++) Rbg[i][j] = (double)pose[bb*16 + i*4 + j];
                tbg[i] = (double)pose[bb*16 + i*4 + 3];
            }
            double Rpr[3][3], Rgt[3][3], tpr[3], tgt[3];
            for (int i = 0; i < 3; i++) {
                for (int j = 0; j < 3; j++) {
                    Rpr[i][j] = Rp[0][0][i]*Rp[bb][0][j] + Rp[0][1][i]*Rp[bb][1][j] + Rp[0][2][i]*Rp[bb][2][j];
                    Rgt[i][j] = R0g[0][i]*Rbg[0][j] + R0g[1][i]*Rbg[1][j] + R0g[2][i]*Rbg[2][j];
                }
                tpr[i] = Rp[0][0][i]*(tp[bb][0]-tp[0][0]) + Rp[0][1][i]*(tp[bb][1]-tp[0][1]) + Rp[0][2][i]*(tp[bb][2]-tp[0][2]);
                tgt[i] = R0g[0][i]*(tbg[0]-t0g[0]) + R0g[1][i]*(tbg[1]-t0g[1]) + R0g[2][i]*(tbg[2]-t0g[2]);
            }
            double trc = 0.0;
            for (int i = 0; i < 3; i++)
                for (int j = 0; j < 3; j++) trc += Rpr[i][j]*Rgt[i][j];
            double cosang = 0.5 * (trc - 1.0);
            if (cosang > hi) cosang = hi;
            if (cosang < lo) cosang = lo;
            rot_sum += acos(cosang);

            const double d0 = tpr[0]-tgt[0], d1 = tpr[1]-tgt[1], d2 = tpr[2]-tgt[2];
            trans_sum += sqrt(d0*d0 + d1*d1 + d2*d2);
        }
        const float rot_loss = (float)(rot_sum / (double)BN);
        const float trans_loss = (float)(trans_sum / (double)BN);
        out[0] = rot_loss + trans_loss;
        out[1] = rot_loss;
        out[2] = trans_loss;

        // reset persistent state for the next graph replay
        for (int bb = 0; bb < BN; bb++) {
            g_cnt[bb] = 0u;
            g_iter[bb] = 0u;
            for (int j = 0; j < 9; j++) g_dR[bb][j] = 0.f;
            for (int j = 0; j < 3; j++) g_t[bb][j] = 0.f;
            // g_acc already zeroed by each batch's final solve
        }
        __threadfence();
    }
}

extern "C" void kernel_launch(void* const* d_in, const int* in_sizes, int n_in,
                              void* d_out, int out_size) {
    const float* pts  = (const float*)d_in[0];   // (B,H,W,3)
    const float* conf = (const float*)d_in[1];   // (B,H,W)
    const float* Kin  = (const float*)d_in[2];   // (B,3,3)
    const float* pose = (const float*)d_in[3];   // (B,4,4)
    float* out = (float*)d_out;

    dim3 grid(BPB, BN);
    fused_kernel<<<grid, TPB>>>(pts, conf, Kin, pose, out);
}

// round 6
// speedup vs baseline: 1.4702x; 1.4702x over previous
#include <cuda_runtime.h>
#include <math.h>

#define BN 16
#define HH 288
#define WW 384
#define NPTS (HH*WW)            // 110592
#define NITER 5
#define BPB 27                  // blocks per batch
#define TPB 256
#define NTHB (BPB*TPB)          // 6912 threads per batch
#define NSWEEP 4                // groups-of-4 sweeps: 6912*4*4 = 110592
#define NACC 26                 // 20 unique nonzero JTJ + 6 JTr

// persistent device state (zero at module load; cleaned up in-kernel each launch)
__device__ double   g_acc[NITER][BN][NACC];
__device__ unsigned g_cnt[NITER][BN];    // arrivals after accumulate
__device__ unsigned g_cnt2[NITER][BN];   // arrivals after local solve
__device__ float    g_Rt[BN][12];        // final pose per batch (R 9 + t 3)
__device__ unsigned g_final[BN];

__device__ __forceinline__ unsigned ld_acq(const unsigned* p) {
    unsigned v;
    asm volatile("ld.global.acquire.gpu.u32 %0, [%1];" : "=r"(v) : "l"(p) : "memory");
    return v;
}
__device__ __forceinline__ void st_rel(unsigned* p, unsigned v) {
    asm volatile("st.global.release.gpu.u32 [%0], %1;" :: "l"(p), "r"(v) : "memory");
}
__device__ __forceinline__ float frsqrt_fast(float x) {
    float r; asm("rsqrt.approx.f32 %0, %1;" : "=f"(r) : "f"(x)); return r;
}

// acc slot map (upper-tri, (0,1) structurally zero):
// (0,0)=0 (0,2)=1 (0,3)=2 (0,4)=3 (0,5)=4 (1,1)=5 (1,2)=6 (1,3)=7 (1,4)=8 (1,5)=9
// (2,2)=10 (2,3)=11 (2,4)=12 (2,5)=13 (3,3)=14 (3,4)=15 (3,5)=16 (4,4)=17 (4,5)=18 (5,5)=19
// JTr: 20..25

// float 6x6 LM solve + SE(3) update of (R,t) in registers
__device__ void solve_update_f32(const float* m, float R[9], float t[3]) {
    float A[6][7];
    A[0][0]=m[0]; A[0][1]=0.f;  A[0][2]=m[1];  A[0][3]=m[2];  A[0][4]=m[3];  A[0][5]=m[4];
    A[1][0]=0.f;  A[1][1]=m[5]; A[1][2]=m[6];  A[1][3]=m[7];  A[1][4]=m[8];  A[1][5]=m[9];
    A[2][0]=m[1]; A[2][1]=m[6]; A[2][2]=m[10]; A[2][3]=m[11]; A[2][4]=m[12]; A[2][5]=m[13];
    A[3][0]=m[2]; A[3][1]=m[7]; A[3][2]=m[11]; A[3][3]=m[14]; A[3][4]=m[15]; A[3][5]=m[16];
    A[4][0]=m[3]; A[4][1]=m[8]; A[4][2]=m[12]; A[4][3]=m[15]; A[4][4]=m[17]; A[4][5]=m[18];
    A[5][0]=m[4]; A[5][1]=m[9]; A[5][2]=m[13]; A[5][3]=m[16]; A[5][4]=m[18]; A[5][5]=m[19];

    const float tr = A[0][0]+A[1][1]+A[2][2]+A[3][3]+A[4][4]+A[5][5];
    const float damp = 1e-4f * tr / 6.0f + 1e-6f;
    for (int i = 0; i < 6; i++) { A[i][i] += damp; A[i][6] = -m[20 + i]; }

    // Gaussian elimination with partial pivoting (float)
    for (int col = 0; col < 6; col++) {
        int piv = col; float best = fabsf(A[col][col]);
        for (int r = col + 1; r < 6; r++) {
            float v = fabsf(A[r][col]);
            if (v > best) { best = v; piv = r; }
        }
        if (piv != col)
            for (int q = col; q < 7; q++) { float tmp = A[col][q]; A[col][q] = A[piv][q]; A[piv][q] = tmp; }
        const float inv = 1.0f / A[col][col];
        for (int r = col + 1; r < 6; r++) {
            const float f = A[r][col] * inv;
            for (int q = col; q < 7; q++) A[r][q] -= f * A[col][q];
        }
    }
    float dx[6];
    for (int i = 5; i >= 0; i--) {
        float s = A[i][6];
        for (int j = i + 1; j < 6; j++) s -= A[i][j] * dx[j];
        dx[i] = s / A[i][i];
    }

    t[0] += dx[0]; t[1] += dx[1]; t[2] += dx[2];

    // R = exp_so3(dx[3:]) @ R  (float, like the reference)
    const float wx = dx[3], wy = dx[4], wz = dx[5];
    float th = sqrtf(wx*wx + wy*wy + wz*wz);
    if (th < 1e-8f) th = 1e-8f;
    const float ux = wx/th, uy = wy/th, uz = wz/th;
    const float st = sinf(th), ct = cosf(th), vt = 1.0f - ct;
    const float E[3][3] = {
        { ct + vt*ux*ux,      vt*ux*uy - st*uz, vt*ux*uz + st*uy },
        { vt*uy*ux + st*uz,   ct + vt*uy*uy,    vt*uy*uz - st*ux },
        { vt*uz*ux - st*uy,   vt*uz*uy + st*ux, ct + vt*uz*uz }
    };
    float Rn[9];
    for (int i = 0; i < 3; i++)
        for (int j = 0; j < 3; j++)
            Rn[i*3+j] = E[i][0]*R[0*3+j] + E[i][1]*R[1*3+j] + E[i][2]*R[2*3+j];
    for (int k = 0; k < 9; k++) R[k] = Rn[k];
}

__global__ void __launch_bounds__(TPB, 3) fused_kernel(
    const float* __restrict__ pts,
    const float* __restrict__ conf,
    const float* __restrict__ Kin,
    const float* __restrict__ pose,
    float* __restrict__ out)
{
    const int b = blockIdx.y;
    const int tid = threadIdx.x;

    const float fx = Kin[b*9 + 0], cx = Kin[b*9 + 2];
    const float fy = Kin[b*9 + 4], cy = Kin[b*9 + 5];

    const float delta = 0.1f * sqrtf(((float)WW*(float)WW - 1.f)/12.f +
                                     ((float)HH*(float)HH - 1.f)/12.f);

    // 4 consecutive points per thread per sweep
    const int g0 = blockIdx.x * TPB + tid;          // 0..6911
    const float px_base = (float)(4 * (g0 % 96));   // invariant across sweeps
    const int   py0 = g0 / 96;                      // py = py0 + 72*sweep

    const float4* __restrict__ P4 = (const float4*)(pts + (size_t)b * NPTS * 3);
    const float4* __restrict__ C4 = (const float4*)(conf + (size_t)b * NPTS);

    __shared__ float sRt[12];
    __shared__ float sm[TPB/32][NACC];

    if (tid == 0) {
        sRt[0]=1.f; sRt[1]=0.f; sRt[2]=0.f;
        sRt[3]=0.f; sRt[4]=1.f; sRt[5]=0.f;
        sRt[6]=0.f; sRt[7]=0.f; sRt[8]=1.f;
        sRt[9]=0.f; sRt[10]=0.f; sRt[11]=0.f;
    }
    __syncthreads();

    for (int it = 0; it < NITER; it++) {
        const float R00 = sRt[0], R01 = sRt[1], R02 = sRt[2];
        const float R10 = sRt[3], R11 = sRt[4], R12 = sRt[5];
        const float R20 = sRt[6], R21 = sRt[7], R22 = sRt[8];
        const float t0 = sRt[9], t1 = sRt[10], t2 = sRt[11];

        float acc[NACC];
#pragma unroll
        for (int k = 0; k < NACC; k++) acc[k] = 0.f;

        auto point = [&](float p0, float p1, float p2, float w, float px, float py) {
            const float X  = fmaf(R00, p0, fmaf(R01, p1, fmaf(R02, p2, t0)));
            const float Y  = fmaf(R10, p0, fmaf(R11, p1, fmaf(R12, p2, t1)));
            const float Zc = fmaf(R20, p0, fmaf(R21, p1, fmaf(R22, p2, t2)));
            const float z  = fmaxf(Zc, 0.01f);
            const float iz = __fdividef(1.0f, z);

            const float fxiz = fx * iz, fyiz = fy * iz;
            const float rx = fmaf(fxiz, X, cx) - px;
            const float ry = fmaf(fyiz, Y, cy) - py;
            const float wrx = w * rx, wry = w * ry;
            const float q  = fmaf(wrx, wrx, wry * wry);
            const float inv_rn = frsqrt_fast(fmaxf(q, 1e-16f));
            const float s = (w * w) * fminf(1.f, delta * inv_rn);

            const float u0 = fxiz;
            const float u2 = -fxiz * (X * iz);
            const float u3 = u2 * Y;
            const float u4 = fmaf(u0, Zc, -u2 * X);
            const float u5 = -u0 * Y;
            const float v1 = fyiz;
            const float v2 = -fyiz * (Y * iz);
            const float v3 = fmaf(v2, Y, -v1 * Zc);
            const float v4 = -v2 * X;
            const float v5 = v1 * X;

            const float su0 = s*u0, su2 = s*u2, su3 = s*u3, su4 = s*u4, su5 = s*u5;
            const float sv1 = s*v1, sv2 = s*v2, sv3 = s*v3, sv4 = s*v4, sv5 = s*v5;

            acc[0]  = fmaf(su0, u0, acc[0]);
            acc[1]  = fmaf(su0, u2, acc[1]);
            acc[2]  = fmaf(su0, u3, acc[2]);
            acc[3]  = fmaf(su0, u4, acc[3]);
            acc[4]  = fmaf(su0, u5, acc[4]);
            acc[5]  = fmaf(sv1, v1, acc[5]);
            acc[6]  = fmaf(sv1, v2, acc[6]);
            acc[7]  = fmaf(sv1, v3, acc[7]);
            acc[8]  = fmaf(sv1, v4, acc[8]);
            acc[9]  = fmaf(sv1, v5, acc[9]);
            acc[10] = fmaf(su2, u2, fmaf(sv2, v2, acc[10]));
            acc[11] = fmaf(su2, u3, fmaf(sv2, v3, acc[11]));
            acc[12] = fmaf(su2, u4, fmaf(sv2, v4, acc[12]));
            acc[13] = fmaf(su2, u5, fmaf(sv2, v5, acc[13]));
            acc[14] = fmaf(su3, u3, fmaf(sv3, v3, acc[14]));
            acc[15] = fmaf(su3, u4, fmaf(sv3, v4, acc[15]));
            acc[16] = fmaf(su3, u5, fmaf(sv3, v5, acc[16]));
            acc[17] = fmaf(su4, u4, fmaf(sv4, v4, acc[17]));
            acc[18] = fmaf(su4, u5, fmaf(sv4, v5, acc[18]));
            acc[19] = fmaf(su5, u5, fmaf(sv5, v5, acc[19]));

            const float srx = s * rx, sry = s * ry;
            acc[20] = fmaf(srx, u0, acc[20]);
            acc[21] = fmaf(sry, v1, acc[21]);
            acc[22] = fmaf(srx, u2, fmaf(sry, v2, acc[22]));
            acc[23] = fmaf(srx, u3, fmaf(sry, v3, acc[23]));
            acc[24] = fmaf(srx, u4, fmaf(sry, v4, acc[24]));
            acc[25] = fmaf(srx, u5, fmaf(sry, v5, acc[25]));
        };

#pragma unroll 2
        for (int k = 0; k < NSWEEP; k++) {
            const int g = g0 + k * NTHB;
            const float4 A = P4[3*g + 0];
            const float4 Bv = P4[3*g + 1];
            const float4 C = P4[3*g + 2];
            const float4 Wv = C4[g];
            const float py = (float)(py0 + 72 * k);
            point(A.x, A.y, A.z, Wv.x, px_base + 0.f, py);
            point(A.w, Bv.x, Bv.y, Wv.y, px_base + 1.f, py);
            point(Bv.z, Bv.w, C.x, Wv.z, px_base + 2.f, py);
            point(C.y, C.z, C.w, Wv.w, px_base + 3.f, py);
        }

        // warp tree-reduce each of NACC sums
#pragma unroll
        for (int k = 0; k < NACC; k++) {
            float v = acc[k];
#pragma unroll
            for (int o = 16; o > 0; o >>= 1) v += __shfl_down_sync(0xffffffffu, v, o);
            acc[k] = v;
        }
        const int wid = tid >> 5, lane = tid & 31;
        if (lane == 0) {
#pragma unroll
            for (int k = 0; k < NACC; k++) sm[wid][k] = acc[k];
        }
        __syncthreads();
        if (tid < NACC) {
            double v = 0.0;
#pragma unroll
            for (int wv = 0; wv < TPB/32; wv++) v += (double)sm[wv][tid];
            atomicAdd(&g_acc[it][b][tid], v);
            __threadfence();   // writer-side fence: red visible before counter bump
        }
        __syncthreads();

        // per-(it,b) barrier + redundant local solve on thread 0
        if (tid == 0) {
            unsigned oldc = atomicAdd(&g_cnt[it][b], 1u);
            if (oldc + 1u < (unsigned)BPB)
                while (ld_acq(&g_cnt[it][b]) < (unsigned)BPB) __nanosleep(32);
            __threadfence();

            float m[NACC];
#pragma unroll
            for (int k = 0; k < NACC; k++) m[k] = (float)__ldcg(&g_acc[it][b][k]);
            __threadfence();   // reads of g_acc complete before cleanup ticket

            float R[9], t[3];
#pragma unroll
            for (int k = 0; k < 9; k++) R[k] = sRt[k];
#pragma unroll
            for (int k = 0; k < 3; k++) t[k] = sRt[9+k];

            solve_update_f32(m, R, t);

#pragma unroll
            for (int k = 0; k < 9; k++) sRt[k] = R[k];
#pragma unroll
            for (int k = 0; k < 3; k++) sRt[9+k] = t[k];

            // cleanup ticket: last block to finish reading zeroes this slot
            unsigned o2 = atomicAdd(&g_cnt2[it][b], 1u);
            if (o2 == (unsigned)(BPB - 1)) {
#pragma unroll
                for (int k = 0; k < NACC; k++) g_acc[it][b][k] = 0.0;
                g_cnt[it][b] = 0u;
                g_cnt2[it][b] = 0u;
                if (it == NITER - 1) {
#pragma unroll
                    for (int k = 0; k < 12; k++) g_Rt[b][k] = (k < 9 ? R[k] : t[k-9]);
                    __threadfence();
                    st_rel(&g_final[b], 1u);
                }
            }
        }
        __syncthreads();
    }

    // -------- final loss (block (0,0), thread 0) --------
    if (blockIdx.x == 0 && blockIdx.y == 0 && tid == 0) {
        for (int bb = 0; bb < BN; bb++)
            while (ld_acq(&g_final[bb]) == 0u) __nanosleep(64);
        __threadfence();

        double Rp[BN][3][3], tp[BN][3];
        for (int bb = 0; bb < BN; bb++) {
            for (int i = 0; i < 3; i++) {
                for (int j = 0; j < 3; j++)
                    Rp[bb][i][j] = (double)__ldcg(&g_Rt[bb][i*3+j]);
                tp[bb][i] = (double)__ldcg(&g_Rt[bb][9+i]);
            }
        }

        const double hi = (double)(float)(1.0 - 1e-7);
        const double lo = (double)(float)(-1.0 + 1e-7);

        double R0g[3][3], t0g[3];
        for (int i = 0; i < 3; i++) {
            for (int j = 0; j < 3; j++) R0g[i][j] = (double)pose[i*4+j];
            t0g[i] = (double)pose[i*4+3];
        }

        double rot_sum = 0.0, trans_sum = 0.0;
        for (int bb = 0; bb < BN; bb++) {
            double Rbg[3][3], tbg[3];
            for (int i = 0; i < 3; i++) {
                for (int j = 0; j < 3; j++) Rbg[i][j] = (double)pose[bb*16 + i*4 + j];
                tbg[i] = (double)pose[bb*16 + i*4 + 3];
            }
            double Rpr[3][3], Rgt[3][3], tpr[3], tgt[3];
            for (int i = 0; i < 3; i++) {
                for (int j = 0; j < 3; j++) {
                    Rpr[i][j] = Rp[0][0][i]*Rp[bb][0][j] + Rp[0][1][i]*Rp[bb][1][j] + Rp[0][2][i]*Rp[bb][2][j];
                    Rgt[i][j] = R0g[0][i]*Rbg[0][j] + R0g[1][i]*Rbg[1][j] + R0g[2][i]*Rbg[2][j];
                }
                tpr[i] = Rp[0][0][i]*(tp[bb][0]-tp[0][0]) + Rp[0][1][i]*(tp[bb][1]-tp[0][1]) + Rp[0][2][i]*(tp[bb][2]-tp[0][2]);
                tgt[i] = R0g[0][i]*(tbg[0]-t0g[0]) + R0g[1][i]*(tbg[1]-t0g[1]) + R0g[2][i]*(tbg[2]-t0g[2]);
            }
            double trc = 0.0;
            for (int i = 0; i < 3; i++)
                for (int j = 0; j < 3; j++) trc += Rpr[i][j]*Rgt[i][j];
            double cosang = 0.5 * (trc - 1.0);
            if (cosang > hi) cosang = hi;
            if (cosang < lo) cosang = lo;
            rot_sum += acos(cosang);

            const double d0 = tpr[0]-tgt[0], d1 = tpr[1]-tgt[1], d2 = tpr[2]-tgt[2];
            trans_sum += sqrt(d0*d0 + d1*d1 + d2*d2);
        }
        const float rot_loss = (float)(rot_sum / (double)BN);
        const float trans_loss = (float)(trans_sum / (double)BN);
        out[0] = rot_loss + trans_loss;
        out[1] = rot_loss;
        out[2] = trans_loss;

        // reset flags for next graph replay
        for (int bb = 0; bb < BN; bb++) g_final[bb] = 0u;
        __threadfence();
    }
}

extern "C" void kernel_launch(void* const* d_in, const int* in_sizes, int n_in,
                              void* d_out, int out_size) {
    const float* pts  = (const float*)d_in[0];   // (B,H,W,3)
    const float* conf = (const float*)d_in[1];   // (B,H,W)
    const float* Kin  = (const float*)d_in[2];   // (B,3,3)
    const float* pose = (const float*)d_in[3];   // (B,4,4)
    float* out = (float*)d_out;

    dim3 grid(BPB, BN);
    fused_kernel<<<grid, TPB>>>(pts, conf, Kin, pose, out);
}

// round 17
// speedup vs baseline: 1.5255x; 1.0376x over previous
#include <cuda_runtime.h>
#include <math.h>

#define BN 16
#define HH 288
#define WW 384
#define NPTS (HH*WW)            // 110592
#define NITER 5
#define BPB 27                  // blocks per batch
#define TPB 256
#define NTHB (BPB*TPB)          // 6912 threads per batch
#define NSWEEP 4                // groups-of-4 sweeps: 6912*4*4 = 110592
#define NACC 26                 // 20 unique nonzero JTJ + 6 JTr

// persistent device state (zero at module load; cleaned up in-kernel each launch)
__device__ double   g_acc[NITER][BN][NACC];
__device__ unsigned g_cnt[NITER][BN];    // arrivals after accumulate
__device__ unsigned g_cnt2[NITER][BN];   // arrivals after local solve
__device__ float    g_Rt[BN][12];        // final pose per batch (R 9 + t 3)
__device__ unsigned g_final[BN];

__device__ __forceinline__ unsigned ld_acq(const unsigned* p) {
    unsigned v;
    asm volatile("ld.global.acquire.gpu.u32 %0, [%1];" : "=r"(v) : "l"(p) : "memory");
    return v;
}
__device__ __forceinline__ void st_rel(unsigned* p, unsigned v) {
    asm volatile("st.global.release.gpu.u32 [%0], %1;" :: "l"(p), "r"(v) : "memory");
}
__device__ __forceinline__ float frsqrt_fast(float x) {
    float r; asm("rsqrt.approx.f32 %0, %1;" : "=f"(r) : "f"(x)); return r;
}

// acc slot map (upper-tri, (0,1) structurally zero):
// (0,0)=0 (0,2)=1 (0,3)=2 (0,4)=3 (0,5)=4 (1,1)=5 (1,2)=6 (1,3)=7 (1,4)=8 (1,5)=9
// (2,2)=10 (2,3)=11 (2,4)=12 (2,5)=13 (3,3)=14 (3,4)=15 (3,5)=16 (4,4)=17 (4,5)=18 (5,5)=19
// JTr: 20..25

// float 6x6 LM solve (Cholesky, fully unrolled -> registers) + SE(3) update
__device__ __forceinline__ void solve_update_f32(const float* m, float R[9], float t[3]) {
    float A[6][6];
    A[0][0]=m[0]; A[0][1]=0.f;  A[0][2]=m[1];  A[0][3]=m[2];  A[0][4]=m[3];  A[0][5]=m[4];
    A[1][0]=0.f;  A[1][1]=m[5]; A[1][2]=m[6];  A[1][3]=m[7];  A[1][4]=m[8];  A[1][5]=m[9];
    A[2][0]=m[1]; A[2][1]=m[6]; A[2][2]=m[10]; A[2][3]=m[11]; A[2][4]=m[12]; A[2][5]=m[13];
    A[3][0]=m[2]; A[3][1]=m[7]; A[3][2]=m[11]; A[3][3]=m[14]; A[3][4]=m[15]; A[3][5]=m[16];
    A[4][0]=m[3]; A[4][1]=m[8]; A[4][2]=m[12]; A[4][3]=m[15]; A[4][4]=m[17]; A[4][5]=m[18];
    A[5][0]=m[4]; A[5][1]=m[9]; A[5][2]=m[13]; A[5][3]=m[16]; A[5][4]=m[18]; A[5][5]=m[19];

    const float tr = A[0][0]+A[1][1]+A[2][2]+A[3][3]+A[4][4]+A[5][5];
    const float damp = 1e-4f * tr / 6.0f + 1e-6f;
    float bv[6];
#pragma unroll
    for (int i = 0; i < 6; i++) { A[i][i] += damp; bv[i] = -m[20 + i]; }

    // Cholesky A = L L^T (L stored in lower A; Linv = 1/diag(L)).
    // All indices static after unroll -> stays in registers.
    float Linv[6];
#pragma unroll
    for (int i = 0; i < 6; i++) {
#pragma unroll
        for (int j = 0; j < 6; j++) {
            if (j > i) continue;
            float s = A[i][j];
#pragma unroll
            for (int k = 0; k < 6; k++) { if (k < j) s -= A[i][k] * A[j][k]; }
            if (i == j) {
                const float inv = frsqrt_fast(fmaxf(s, 1e-30f));
                Linv[i] = inv;
                A[i][i] = s * inv;          // = sqrt(s)
            } else {
                A[i][j] = s * Linv[j];
            }
        }
    }
    // forward: L y = b
    float y[6];
#pragma unroll
    for (int i = 0; i < 6; i++) {
        float s = bv[i];
#pragma unroll
        for (int k = 0; k < 6; k++) { if (k < i) s -= A[i][k] * y[k]; }
        y[i] = s * Linv[i];
    }
    // backward: L^T dx = y
    float dx[6];
#pragma unroll
    for (int ii = 5; ii >= 0; ii--) {
        float s = y[ii];
#pragma unroll
        for (int k = 0; k < 6; k++) { if (k > ii) s -= A[k][ii] * dx[k]; }
        dx[ii] = s * Linv[ii];
    }

    t[0] += dx[0]; t[1] += dx[1]; t[2] += dx[2];

    // R = exp_so3(dx[3:]) @ R  (float; MUFU trig)
    const float wx = dx[3], wy = dx[4], wz = dx[5];
    float th = sqrtf(wx*wx + wy*wy + wz*wz);
    if (th < 1e-8f) th = 1e-8f;
    const float ith = __fdividef(1.0f, th);
    const float ux = wx*ith, uy = wy*ith, uz = wz*ith;
    const float st = __sinf(th), ct = __cosf(th), vt = 1.0f - ct;
    const float E[3][3] = {
        { ct + vt*ux*ux,      vt*ux*uy - st*uz, vt*ux*uz + st*uy },
        { vt*uy*ux + st*uz,   ct + vt*uy*uy,    vt*uy*uz - st*ux },
        { vt*uz*ux - st*uy,   vt*uz*uy + st*ux, ct + vt*uz*uz }
    };
    float Rn[9];
#pragma unroll
    for (int i = 0; i < 3; i++)
#pragma unroll
        for (int j = 0; j < 3; j++)
            Rn[i*3+j] = E[i][0]*R[0*3+j] + E[i][1]*R[1*3+j] + E[i][2]*R[2*3+j];
#pragma unroll
    for (int k = 0; k < 9; k++) R[k] = Rn[k];
}

__global__ void __launch_bounds__(TPB, 3) fused_kernel(
    const float* __restrict__ pts,
    const float* __restrict__ conf,
    const float* __restrict__ Kin,
    const float* __restrict__ pose,
    float* __restrict__ out)
{
    const int b = blockIdx.y;
    const int tid = threadIdx.x;

    const float fx = Kin[b*9 + 0], cx = Kin[b*9 + 2];
    const float fy = Kin[b*9 + 4], cy = Kin[b*9 + 5];

    const float delta = 0.1f * sqrtf(((float)WW*(float)WW - 1.f)/12.f +
                                     ((float)HH*(float)HH - 1.f)/12.f);

    // 4 consecutive points per thread per sweep
    const int g0 = blockIdx.x * TPB + tid;          // 0..6911
    const float px_base = (float)(4 * (g0 % 96));   // invariant across sweeps
    const int   py0 = g0 / 96;                      // py = py0 + 72*sweep

    const float4* __restrict__ P4 = (const float4*)(pts + (size_t)b * NPTS * 3);
    const float4* __restrict__ C4 = (const float4*)(conf + (size_t)b * NPTS);

    __shared__ float sRt[12];
    __shared__ float sm[TPB/32][NACC];

    if (tid == 0) {
        sRt[0]=1.f; sRt[1]=0.f; sRt[2]=0.f;
        sRt[3]=0.f; sRt[4]=1.f; sRt[5]=0.f;
        sRt[6]=0.f; sRt[7]=0.f; sRt[8]=1.f;
        sRt[9]=0.f; sRt[10]=0.f; sRt[11]=0.f;
    }
    __syncthreads();

    for (int it = 0; it < NITER; it++) {
        const float R00 = sRt[0], R01 = sRt[1], R02 = sRt[2];
        const float R10 = sRt[3], R11 = sRt[4], R12 = sRt[5];
        const float R20 = sRt[6], R21 = sRt[7], R22 = sRt[8];
        const float t0 = sRt[9], t1 = sRt[10], t2 = sRt[11];

        float acc[NACC];
#pragma unroll
        for (int k = 0; k < NACC; k++) acc[k] = 0.f;

        auto point = [&](float p0, float p1, float p2, float w, float px, float py) {
            const float X  = fmaf(R00, p0, fmaf(R01, p1, fmaf(R02, p2, t0)));
            const float Y  = fmaf(R10, p0, fmaf(R11, p1, fmaf(R12, p2, t1)));
            const float Zc = fmaf(R20, p0, fmaf(R21, p1, fmaf(R22, p2, t2)));
            const float z  = fmaxf(Zc, 0.01f);
            const float iz = __fdividef(1.0f, z);

            const float fxiz = fx * iz, fyiz = fy * iz;
            const float rx = fmaf(fxiz, X, cx) - px;
            const float ry = fmaf(fyiz, Y, cy) - py;
            const float wrx = w * rx, wry = w * ry;
            const float q  = fmaf(wrx, wrx, wry * wry);
            const float inv_rn = frsqrt_fast(fmaxf(q, 1e-16f));
            const float s = (w * w) * fminf(1.f, delta * inv_rn);

            const float u0 = fxiz;
            const float u2 = -fxiz * (X * iz);
            const float u3 = u2 * Y;
            const float u4 = fmaf(u0, Zc, -u2 * X);
            const float u5 = -u0 * Y;
            const float v1 = fyiz;
            const float v2 = -fyiz * (Y * iz);
            const float v3 = fmaf(v2, Y, -v1 * Zc);
            const float v4 = -v2 * X;
            const float v5 = v1 * X;

            const float su0 = s*u0, su2 = s*u2, su3 = s*u3, su4 = s*u4, su5 = s*u5;
            const float sv1 = s*v1, sv2 = s*v2, sv3 = s*v3, sv4 = s*v4, sv5 = s*v5;

            acc[0]  = fmaf(su0, u0, acc[0]);
            acc[1]  = fmaf(su0, u2, acc[1]);
            acc[2]  = fmaf(su0, u3, acc[2]);
            acc[3]  = fmaf(su0, u4, acc[3]);
            acc[4]  = fmaf(su0, u5, acc[4]);
            acc[5]  = fmaf(sv1, v1, acc[5]);
            acc[6]  = fmaf(sv1, v2, acc[6]);
            acc[7]  = fmaf(sv1, v3, acc[7]);
            acc[8]  = fmaf(sv1, v4, acc[8]);
            acc[9]  = fmaf(sv1, v5, acc[9]);
            acc[10] = fmaf(su2, u2, fmaf(sv2, v2, acc[10]));
            acc[11] = fmaf(su2, u3, fmaf(sv2, v3, acc[11]));
            acc[12] = fmaf(su2, u4, fmaf(sv2, v4, acc[12]));
            acc[13] = fmaf(su2, u5, fmaf(sv2, v5, acc[13]));
            acc[14] = fmaf(su3, u3, fmaf(sv3, v3, acc[14]));
            acc[15] = fmaf(su3, u4, fmaf(sv3, v4, acc[15]));
            acc[16] = fmaf(su3, u5, fmaf(sv3, v5, acc[16]));
            acc[17] = fmaf(su4, u4, fmaf(sv4, v4, acc[17]));
            acc[18] = fmaf(su4, u5, fmaf(sv4, v5, acc[18]));
            acc[19] = fmaf(su5, u5, fmaf(sv5, v5, acc[19]));

            const float srx = s * rx, sry = s * ry;
            acc[20] = fmaf(srx, u0, acc[20]);
            acc[21] = fmaf(sry, v1, acc[21]);
            acc[22] = fmaf(srx, u2, fmaf(sry, v2, acc[22]));
            acc[23] = fmaf(srx, u3, fmaf(sry, v3, acc[23]));
            acc[24] = fmaf(srx, u4, fmaf(sry, v4, acc[24]));
            acc[25] = fmaf(srx, u5, fmaf(sry, v5, acc[25]));
        };

#pragma unroll 2
        for (int k = 0; k < NSWEEP; k++) {
            const int g = g0 + k * NTHB;
            const float4 A = P4[3*g + 0];
            const float4 Bv = P4[3*g + 1];
            const float4 C = P4[3*g + 2];
            const float4 Wv = C4[g];
            const float py = (float)(py0 + 72 * k);
            point(A.x, A.y, A.z, Wv.x, px_base + 0.f, py);
            point(A.w, Bv.x, Bv.y, Wv.y, px_base + 1.f, py);
            point(Bv.z, Bv.w, C.x, Wv.z, px_base + 2.f, py);
            point(C.y, C.z, C.w, Wv.w, px_base + 3.f, py);
        }

        // warp tree-reduce each of NACC sums
#pragma unroll
        for (int k = 0; k < NACC; k++) {
            float v = acc[k];
#pragma unroll
            for (int o = 16; o > 0; o >>= 1) v += __shfl_down_sync(0xffffffffu, v, o);
            acc[k] = v;
        }
        const int wid = tid >> 5, lane = tid & 31;
        if (lane == 0) {
#pragma unroll
            for (int k = 0; k < NACC; k++) sm[wid][k] = acc[k];
        }
        __syncthreads();
        if (tid < NACC) {
            double v = 0.0;
#pragma unroll
            for (int wv = 0; wv < TPB/32; wv++) v += (double)sm[wv][tid];
            atomicAdd(&g_acc[it][b][tid], v);
            __threadfence();   // writer-side fence: red visible before counter bump
        }
        __syncthreads();

        // per-(it,b) barrier + redundant local solve on thread 0
        if (tid == 0) {
            unsigned oldc = atomicAdd(&g_cnt[it][b], 1u);
            if (oldc + 1u < (unsigned)BPB)
                while (ld_acq(&g_cnt[it][b]) < (unsigned)BPB) __nanosleep(32);
            __threadfence();

            float m[NACC];
#pragma unroll
            for (int k = 0; k < NACC; k++) m[k] = (float)__ldcg(&g_acc[it][b][k]);
            __threadfence();   // reads of g_acc complete before cleanup ticket

            float R[9], t[3];
#pragma unroll
            for (int k = 0; k < 9; k++) R[k] = sRt[k];
#pragma unroll
            for (int k = 0; k < 3; k++) t[k] = sRt[9+k];

            solve_update_f32(m, R, t);

#pragma unroll
            for (int k = 0; k < 9; k++) sRt[k] = R[k];
#pragma unroll
            for (int k = 0; k < 3; k++) sRt[9+k] = t[k];

            // cleanup ticket: last block to finish reading zeroes this slot
            unsigned o2 = atomicAdd(&g_cnt2[it][b], 1u);
            if (o2 == (unsigned)(BPB - 1)) {
#pragma unroll
                for (int k = 0; k < NACC; k++) g_acc[it][b][k] = 0.0;
                g_cnt[it][b] = 0u;
                g_cnt2[it][b] = 0u;
                if (it == NITER - 1) {
#pragma unroll
                    for (int k = 0; k < 12; k++) g_Rt[b][k] = (k < 9 ? R[k] : t[k-9]);
                    __threadfence();
                    st_rel(&g_final[b], 1u);
                }
            }
        }
        __syncthreads();
    }

    // -------- final loss (block (0,0), thread 0) --------
    if (blockIdx.x == 0 && blockIdx.y == 0 && tid == 0) {
        for (int bb = 0; bb < BN; bb++)
            while (ld_acq(&g_final[bb]) == 0u) __nanosleep(64);
        __threadfence();

        double Rp[BN][3][3], tp[BN][3];
        for (int bb = 0; bb < BN; bb++) {
            for (int i = 0; i < 3; i++) {
                for (int j = 0; j < 3; j++)
                    Rp[bb][i][j] = (double)__ldcg(&g_Rt[bb][i*3+j]);
                tp[bb][i] = (double)__ldcg(&g_Rt[bb][9+i]);
            }
        }

        const double hi = (double)(float)(1.0 - 1e-7);
        const double lo = (double)(float)(-1.0 + 1e-7);

        double R0g[3][3], t0g[3];
        for (int i = 0; i < 3; i++) {
            for (int j = 0; j < 3; j++) R0g[i][j] = (double)pose[i*4+j];
            t0g[i] = (double)pose[i*4+3];
        }

        double rot_sum = 0.0, trans_sum = 0.0;
        for (int bb = 0; bb < BN; bb++) {
            double Rbg[3][3], tbg[3];
            for (int i = 0; i < 3; i++) {
                for (int j = 0; j < 3; j++) Rbg[i][j] = (double)pose[bb*16 + i*4 + j];
                tbg[i] = (double)pose[bb*16 + i*4 + 3];
            }
            double Rpr[3][3], Rgt[3][3], tpr[3], tgt[3];
            for (int i = 0; i < 3; i++) {
                for (int j = 0; j < 3; j++) {
                    Rpr[i][j] = Rp[0][0][i]*Rp[bb][0][j] + Rp[0][1][i]*Rp[bb][1][j] + Rp[0][2][i]*Rp[bb][2][j];
                    Rgt[i][j] = R0g[0][i]*Rbg[0][j] + R0g[1][i]*Rbg[1][j] + R0g[2][i]*Rbg[2][j];
                }
                tpr[i] = Rp[0][0][i]*(tp[bb][0]-tp[0][0]) + Rp[0][1][i]*(tp[bb][1]-tp[0][1]) + Rp[0][2][i]*(tp[bb][2]-tp[0][2]);
                tgt[i] = R0g[0][i]*(tbg[0]-t0g[0]) + R0g[1][i]*(tbg[1]-t0g[1]) + R0g[2][i]*(tbg[2]-t0g[2]);
            }
            double trc = 0.0;
            for (int i = 0; i < 3; i++)
                for (int j = 0; j < 3; j++) trc += Rpr[i][j]*Rgt[i][j];
            double cosang = 0.5 * (trc - 1.0);
            if (cosang > hi) cosang = hi;
            if (cosang < lo) cosang = lo;
            rot_sum += acos(cosang);

            const double d0 = tpr[0]-tgt[0], d1 = tpr[1]-tgt[1], d2 = tpr[2]-tgt[2];
            trans_sum += sqrt(d0*d0 + d1*d1 + d2*d2);
        }
        const float rot_loss = (float)(rot_sum / (double)BN);
        const float trans_loss = (float)(trans_sum / (double)BN);
        out[0] = rot_loss + trans_loss;
        out[1] = rot_loss;
        out[2] = trans_loss;

        // reset flags for next graph replay
        for (int bb = 0; bb < BN; bb++) g_final[bb] = 0u;
        __threadfence();
    }
}

extern "C" void kernel_launch(void* const* d_in, const int* in_sizes, int n_in,
                              void* d_out, int out_size) {
    const float* pts  = (const float*)d_in[0];   // (B,H,W,3)
    const float* conf = (const float*)d_in[1];   // (B,H,W)
    const float* Kin  = (const float*)d_in[2];   // (B,3,3)
    const float* pose = (const float*)d_in[3];   // (B,4,4)
    float* out = (float*)d_out;

    dim3 grid(BPB, BN);
    fused_kernel<<<grid, TPB>>>(pts, conf, Kin, pose, out);
}